// round 2
// baseline (speedup 1.0000x reference)
#include <cuda_runtime.h>
#include <math.h>

#define HB 65536  // H*B floats per (t) state slab

// ---- scratch (__device__ globals; no allocation) ----
__device__ float g_WstackT[512 * 3072];   // [k][j]  j<1024: Wi0+Ws0, <2048: Ws1, else Ws2
__device__ float g_Wc0T[1024 * 1024];     // [k][n] = Wh0[n][k]
__device__ float g_Wc1T[2048 * 1024];     // [k][n]  k<1024: Wi12[0], else Wh1
__device__ float g_Wc2T[2048 * 1024];     // [k][n]  k<1024: Wi12[1], else Wh2
__device__ float g_b0[1024], g_b1[1024], g_b2[1024];
__device__ float g_Y[256 * 3072 * 64];    // [t][j][b]
__device__ float g_A0[256 * HB], g_A1[256 * HB], g_A2[256 * HB];   // [t][h][b]
__device__ float g_H0[257 * HB];          // H0[i] = h0[i-1]; H0[0]=noise0
__device__ float g_H1[256 * HB];          // H1[t] = h1[t];  H1[0]=noise3
__device__ float g_H2[256 * HB];          // H2[t] = h2[t];  H2[2]=noise6
__device__ float g_P[320 * 128 * 64];     // split-K partials [task][n_local][b]

__global__ void prep_kernel(const float* __restrict__ Wi0, const float* __restrict__ Wi12,
                            const float* __restrict__ bi,  const float* __restrict__ Ws,
                            const float* __restrict__ bs,  const float* __restrict__ Wh,
                            const float* __restrict__ bh,  const float* __restrict__ noise) {
    int tid = blockIdx.x * blockDim.x + threadIdx.x, nthr = gridDim.x * blockDim.x;
    for (int i = tid; i < 512 * 3072; i += nthr) {
        int k = i / 3072, j = i % 3072;
        float v;
        if (j < 1024)      v = Wi0[j * 512 + k] + Ws[j * 512 + k];
        else if (j < 2048) v = Ws[524288 + (j - 1024) * 512 + k];
        else               v = Ws[1048576 + (j - 2048) * 512 + k];
        g_WstackT[i] = v;
    }
    for (int i = tid; i < 1024 * 1024; i += nthr) {
        int k = i >> 10, n = i & 1023;
        g_Wc0T[i] = Wh[n * 1024 + k];
    }
    for (int i = tid; i < 2048 * 1024; i += nthr) {
        int k = i >> 10, n = i & 1023;
        g_Wc1T[i] = (k < 1024) ? Wi12[n * 1024 + k] : Wh[1048576 + n * 1024 + (k - 1024)];
        g_Wc2T[i] = (k < 1024) ? Wi12[1048576 + n * 1024 + k] : Wh[2097152 + n * 1024 + (k - 1024)];
    }
    for (int i = tid; i < 1024; i += nthr) {
        g_b0[i] = bi[i] + bs[i] + bh[i];
        g_b1[i] = bi[1024 + i] + bs[1024 + i] + bh[1024 + i];
        g_b2[i] = bi[2048 + i] + bs[2048 + i] + bh[2048 + i];
    }
    for (int i = tid; i < HB; i += nthr) {
        int h = i >> 6, b = i & 63;
        g_H0[i] = noise[b * 1024 + h];
        g_H1[i] = noise[3 * HB + b * 1024 + h];
        g_H2[2 * HB + i] = noise[6 * HB + b * 1024 + h];
    }
}

// Y[t][j][b] = sum_k x[b][t][k] * WstackT[k][j]; tile 128j x 64b, K=512
__global__ void __launch_bounds__(128) gemm1_kernel(const float* __restrict__ x) {
    __shared__ float Ws_[16][128];
    __shared__ float Xs_[16][64];
    const int t = blockIdx.y, jbase = blockIdx.x * 128;
    const int tid = threadIdx.x, tn = tid & 15, tb = tid >> 4;
    float acc[8][8];
#pragma unroll
    for (int a = 0; a < 8; a++)
#pragma unroll
        for (int b = 0; b < 8; b++) acc[a][b] = 0.f;
    for (int kk = 0; kk < 512; kk += 16) {
#pragma unroll
        for (int i = 0; i < 4; i++) {
            int f4 = i * 128 + tid, k = f4 >> 5, n4 = f4 & 31;
            *(float4*)&Ws_[k][n4 * 4] = *(const float4*)&g_WstackT[(kk + k) * 3072 + jbase + n4 * 4];
        }
#pragma unroll
        for (int i = 0; i < 2; i++) {
            int f4 = i * 128 + tid, b = f4 >> 2, k4 = f4 & 3;
            float4 v = *(const float4*)&x[b * (256 * 512) + t * 512 + kk + k4 * 4];
            Xs_[k4 * 4 + 0][b] = v.x; Xs_[k4 * 4 + 1][b] = v.y;
            Xs_[k4 * 4 + 2][b] = v.z; Xs_[k4 * 4 + 3][b] = v.w;
        }
        __syncthreads();
#pragma unroll
        for (int k = 0; k < 16; k++) {
            float nf[8], bf[8];
            *(float4*)&nf[0] = *(float4*)&Ws_[k][tn * 8];
            *(float4*)&nf[4] = *(float4*)&Ws_[k][tn * 8 + 4];
            *(float4*)&bf[0] = *(float4*)&Xs_[k][tb * 8];
            *(float4*)&bf[4] = *(float4*)&Xs_[k][tb * 8 + 4];
#pragma unroll
            for (int a = 0; a < 8; a++)
#pragma unroll
                for (int b = 0; b < 8; b++) acc[a][b] += nf[a] * bf[b];
        }
        __syncthreads();
    }
    float* yb = &g_Y[t * 196608 + jbase * 64];
#pragma unroll
    for (int a = 0; a < 8; a++) {
        int j = tn * 8 + a;
        *(float4*)&yb[j * 64 + tb * 8]     = make_float4(acc[a][0], acc[a][1], acc[a][2], acc[a][3]);
        *(float4*)&yb[j * 64 + tb * 8 + 4] = make_float4(acc[a][4], acc[a][5], acc[a][6], acc[a][7]);
    }
}

__global__ void combine_kernel() {
    int stride = gridDim.x * blockDim.x;
    for (int idx = blockIdx.x * blockDim.x + threadIdx.x; idx < 256 * HB; idx += stride) {
        int t = idx >> 16, r = idx & (HB - 1), h = r >> 6;
        float a0 = (t + 3 < 256) ? g_Y[(t + 3) * 196608 + r] : 0.f;
        g_A0[idx] = a0 + g_b0[h];
        float s1 = ((t + 2 < 256) ? g_Y[(t + 2) * 196608 + 65536 + r] : 0.f) +
                   ((t + 3 < 256) ? g_Y[(t + 3) * 196608 + 65536 + r] : 0.f);
        g_A1[idx] = 0.5f * s1 + g_b1[h];
        float s2 = g_Y[t * 196608 + 131072 + r] +
                   ((t + 1 < 256) ? g_Y[(t + 1) * 196608 + 131072 + r] : 0.f) +
                   ((t + 2 < 256) ? g_Y[(t + 2) * 196608 + 131072 + r] : 0.f) +
                   ((t + 3 < 256) ? g_Y[(t + 3) * 196608 + 131072 + r] : 0.f);
        g_A2[idx] = 0.25f * s2 + g_b2[h];
    }
}

// slot s: L0 t=s, L1 t=s-1, L2 t=s-2; split-K 128; 320 tasks
__global__ void __launch_bounds__(128) slot_gemm_kernel(int s) {
    const int task = blockIdx.x;
    int layer, ntile, kc;
    if (task < 64)       { layer = 0; ntile = task >> 3; kc = task & 7; }
    else if (task < 192) { layer = 1; int r = task - 64;  ntile = r >> 4; kc = r & 15; }
    else                 { layer = 2; int r = task - 192; ntile = r >> 4; kc = r & 15; }
    int t;
    if (layer == 0)      { t = s;     if (t > 255) return; }
    else if (layer == 1) { t = s - 1; if (t < 1 || t > 255) return; }
    else                 { t = s - 2; if (t < 3 || t > 255) return; }
    const int kbase = kc * 128;
    const float* hin;
    if (layer == 0)      hin = g_H0 + t * HB + kbase * 64;
    else if (layer == 1) hin = (kbase < 1024) ? g_H0 + (t + 1) * HB + kbase * 64
                                              : g_H1 + (t - 1) * HB + (kbase - 1024) * 64;
    else                 hin = (kbase < 1024) ? g_H1 + t * HB + kbase * 64
                                              : g_H2 + (t - 1) * HB + (kbase - 1024) * 64;
    const float* w = (layer == 0 ? g_Wc0T : layer == 1 ? g_Wc1T : g_Wc2T) + kbase * 1024 + ntile * 128;
    float* pout = g_P + task * 8192;

    __shared__ float Ws_[16][128];
    __shared__ float Xs_[16][64];
    const int tid = threadIdx.x, tn = tid & 15, tb = tid >> 4;
    float acc[8][8];
#pragma unroll
    for (int a = 0; a < 8; a++)
#pragma unroll
        for (int b = 0; b < 8; b++) acc[a][b] = 0.f;
    for (int kk = 0; kk < 128; kk += 16) {
#pragma unroll
        for (int i = 0; i < 4; i++) {
            int f4 = i * 128 + tid, k = f4 >> 5, n4 = f4 & 31;
            *(float4*)&Ws_[k][n4 * 4] = *(const float4*)&w[(kk + k) * 1024 + n4 * 4];
        }
#pragma unroll
        for (int i = 0; i < 2; i++) {
            int f4 = i * 128 + tid, k = f4 >> 4, b4 = f4 & 15;
            *(float4*)&Xs_[k][b4 * 4] = *(const float4*)&hin[(kk + k) * 64 + b4 * 4];
        }
        __syncthreads();
#pragma unroll
        for (int k = 0; k < 16; k++) {
            float nf[8], bf[8];
            *(float4*)&nf[0] = *(float4*)&Ws_[k][tn * 8];
            *(float4*)&nf[4] = *(float4*)&Ws_[k][tn * 8 + 4];
            *(float4*)&bf[0] = *(float4*)&Xs_[k][tb * 8];
            *(float4*)&bf[4] = *(float4*)&Xs_[k][tb * 8 + 4];
#pragma unroll
            for (int a = 0; a < 8; a++)
#pragma unroll
                for (int b = 0; b < 8; b++) acc[a][b] += nf[a] * bf[b];
        }
        __syncthreads();
    }
#pragma unroll
    for (int a = 0; a < 8; a++) {
        int nl = tn * 8 + a;
        *(float4*)&pout[nl * 64 + tb * 8]     = make_float4(acc[a][0], acc[a][1], acc[a][2], acc[a][3]);
        *(float4*)&pout[nl * 64 + tb * 8 + 4] = make_float4(acc[a][4], acc[a][5], acc[a][6], acc[a][7]);
    }
}

__global__ void slot_reduce_kernel(int s) {
    const int layer = blockIdx.x >> 5;
    int t;
    if (layer == 0)      { t = s;     if (t > 255) return; }
    else if (layer == 1) { t = s - 1; if (t < 1 || t > 255) return; }
    else                 { t = s - 2; if (t < 3 || t > 255) return; }
    const float* A = (layer == 0 ? g_A0 : layer == 1 ? g_A1 : g_A2) + t * HB;
    float* dst = (layer == 0) ? g_H0 + (t + 1) * HB : (layer == 1) ? g_H1 + t * HB : g_H2 + t * HB;
    const int nk = (layer == 0) ? 8 : 16;
    const int tbase = (layer == 0) ? 0 : (layer == 1 ? 64 : 192);
    const int base = (blockIdx.x & 31) * 2048;
    for (int ii = 0; ii < 8; ii++) {
        int r = base + ii * 256 + threadIdx.x;
        int n = r >> 6, b = r & 63, ntile = n >> 7, nl = n & 127;
        float sum = A[r];
        const float* p = g_P + (tbase + ntile * nk) * 8192 + nl * 64 + b;
        if (nk == 8) {
#pragma unroll
            for (int k = 0; k < 8; k++) sum += p[k * 8192];
        } else {
#pragma unroll
            for (int k = 0; k < 16; k++) sum += p[k * 8192];
        }
        dst[r] = tanhf(sum);
    }
}

// out[l][b][i] = sum_h hs[l][h][b]*Wo[i][h] + bo[i]
__global__ void __launch_bounds__(128) out_kernel(const float* __restrict__ Wo,
                                                  const float* __restrict__ bo,
                                                  float* __restrict__ out) {
    __shared__ float Ws_[16][128];
    __shared__ float Xs_[16][64];
    const int l = blockIdx.y, ibase = blockIdx.x * 128;
    const float* hsrc = (l == 0) ? g_H0 + 256 * HB : (l == 1) ? g_H1 + 255 * HB : g_H2 + 255 * HB;
    const int tid = threadIdx.x, tn = tid & 15, tb = tid >> 4;
    float acc[8][8];
#pragma unroll
    for (int a = 0; a < 8; a++)
#pragma unroll
        for (int b = 0; b < 8; b++) acc[a][b] = 0.f;
    for (int kk = 0; kk < 1024; kk += 16) {
#pragma unroll
        for (int i = 0; i < 4; i++) {
            int f4 = i * 128 + tid, irow = f4 >> 2, k4 = f4 & 3;
            float4 v = *(const float4*)&Wo[(ibase + irow) * 1024 + kk + k4 * 4];
            Ws_[k4 * 4 + 0][irow] = v.x; Ws_[k4 * 4 + 1][irow] = v.y;
            Ws_[k4 * 4 + 2][irow] = v.z; Ws_[k4 * 4 + 3][irow] = v.w;
        }
#pragma unroll
        for (int i = 0; i < 2; i++) {
            int f4 = i * 128 + tid, k = f4 >> 4, b4 = f4 & 15;
            *(float4*)&Xs_[k][b4 * 4] = *(const float4*)&hsrc[(kk + k) * 64 + b4 * 4];
        }
        __syncthreads();
#pragma unroll
        for (int k = 0; k < 16; k++) {
            float nf[8], bf[8];
            *(float4*)&nf[0] = *(float4*)&Ws_[k][tn * 8];
            *(float4*)&nf[4] = *(float4*)&Ws_[k][tn * 8 + 4];
            *(float4*)&bf[0] = *(float4*)&Xs_[k][tb * 8];
            *(float4*)&bf[4] = *(float4*)&Xs_[k][tb * 8 + 4];
#pragma unroll
            for (int a = 0; a < 8; a++)
#pragma unroll
                for (int b = 0; b < 8; b++) acc[a][b] += nf[a] * bf[b];
        }
        __syncthreads();
    }
#pragma unroll
    for (int a = 0; a < 8; a++) {
        int i = ibase + tn * 8 + a;
        float bv = bo[i];
#pragma unroll
        for (int b = 0; b < 8; b++)
            out[l * 64 * 512 + (tb * 8 + b) * 512 + i] = acc[a][b] + bv;
    }
}

extern "C" void kernel_launch(void* const* d_in, const int* in_sizes, int n_in,
                              void* d_out, int out_size) {
    const float* x     = (const float*)d_in[0];
    const float* noise = (const float*)d_in[1];
    const float* Wi0   = (const float*)d_in[2];
    const float* Wi12  = (const float*)d_in[3];
    const float* bi    = (const float*)d_in[4];
    const float* Ws    = (const float*)d_in[5];
    const float* bs    = (const float*)d_in[6];
    const float* Wh    = (const float*)d_in[7];
    const float* bh    = (const float*)d_in[8];
    const float* Wo    = (const float*)d_in[9];
    const float* bo    = (const float*)d_in[10];
    float* out = (float*)d_out;

    prep_kernel<<<512, 256>>>(Wi0, Wi12, bi, Ws, bs, Wh, bh, noise);
    gemm1_kernel<<<dim3(24, 256), 128>>>(x);
    combine_kernel<<<2048, 256>>>();
    for (int s = 0; s < 258; s++) {
        slot_gemm_kernel<<<320, 128>>>(s);
        slot_reduce_kernel<<<96, 256>>>(s);
    }
    out_kernel<<<dim3(4, 3), 128>>>(Wo, bo, out);
}